// round 7
// baseline (speedup 1.0000x reference)
#include <cuda_runtime.h>

#define B_TOTAL 4096
#define V_TOTAL 1024
#define DD 64
#define TB 64
#define TV 32
#define NBLOCKS ((B_TOTAL / TB) * (V_TOTAL / TV))

// Zero-initialized scratch. Min stored as key = ~bits(value); dist >= 0 so bit
// order == value order, atomicMax(key) == min(value), 0 is the identity.
// Last block resets everything to 0 -> graph-replay safe.
__device__ unsigned int g_rowmin_key[B_TOTAL];
__device__ unsigned int g_colmin_key[V_TOTAL];
__device__ unsigned int g_arrive;

typedef unsigned long long ull;

__global__ __launch_bounds__(128, 8)
void dist_fused(const float* __restrict__ x, const float* __restrict__ p,
                float* __restrict__ out) {
    // 24 KB: sm[0..2047]      x pairs  XS(kk,row) = sm[kk*64 + row]
    //        sm[2048..3071]   p pairs  PS(kk,tx,j) = sm[2048 + kk*32 + tx*2 + j]
    __shared__ ull sm[3072];

    const int tid = threadIdx.x;
    const int b0 = blockIdx.y * TB;
    const int v0 = blockIdx.x * TV;

    // ---- prologue ----
    if (tid < 64) {
        const float4* __restrict__ xr4 = (const float4*)(x + (size_t)(b0 + tid) * DD);
#pragma unroll
        for (int c4 = 0; c4 < 16; c4++) {
            float4 v = xr4[c4];
            int kk = c4 * 2;
            *(float2*)&sm[kk * 64 + tid]       = make_float2(v.x, v.y);
            *(float2*)&sm[(kk + 1) * 64 + tid] = make_float2(v.z, v.w);
        }
    } else {
        int t = tid - 64;
        int r = t & 31;
        int half = t >> 5;
        int lane16 = r & 15, jslot = r >> 4;
        const float4* __restrict__ pr4 = (const float4*)(p + (size_t)(v0 + r) * DD);
#pragma unroll
        for (int c4i = 0; c4i < 8; c4i++) {
            int c4 = half * 8 + c4i;
            float4 v = pr4[c4];
            int kk = c4 * 2;
            *(float2*)&sm[2048 + kk * 32 + lane16 * 2 + jslot]       = make_float2(-v.x, -v.y);
            *(float2*)&sm[2048 + (kk + 1) * 32 + lane16 * 2 + jslot] = make_float2(-v.z, -v.w);
        }
    }
    __syncthreads();

    const int tx = tid & 15;    // v = tx (j=0), tx+16 (j=1)
    const int ty = tid >> 4;    // rows ty*8 .. ty*8+7
    const int row0 = ty * 8;

    unsigned int xa = (unsigned int)__cvta_generic_to_shared(&sm[row0]);
    unsigned int pa = (unsigned int)__cvta_generic_to_shared(&sm[2048 + tx * 2]);

    // a0..a7 = rows 0..7 vs v=tx ; a8..a15 = rows 0..7 vs v=tx+16
    ull A[16];

    // One asm region, 1 kk per iteration (32 iters) -> small live set (~58 regs)
    // so launch_bounds(128,8) holds 64 regs -> 8 CTAs/SM -> 32 warps.
    asm volatile(
        "{\n\t"
        ".reg .b64 a<16>;\n\t"
        ".reg .b64 xl<8>;\n\t"
        ".reg .b64 p0, p1;\n\t"
        ".reg .b64 t0, t1, t2, t3;\n\t"
        ".reg .b32 xa, pa, k;\n\t"
        ".reg .pred lp;\n\t"
        "mov.b64 a0, 0;  mov.b64 a1, 0;  mov.b64 a2, 0;  mov.b64 a3, 0;\n\t"
        "mov.b64 a4, 0;  mov.b64 a5, 0;  mov.b64 a6, 0;  mov.b64 a7, 0;\n\t"
        "mov.b64 a8, 0;  mov.b64 a9, 0;  mov.b64 a10, 0; mov.b64 a11, 0;\n\t"
        "mov.b64 a12, 0; mov.b64 a13, 0; mov.b64 a14, 0; mov.b64 a15, 0;\n\t"
        "mov.b32 xa, %16;\n\t"
        "mov.b32 pa, %17;\n\t"
        "mov.b32 k, 0;\n\t"
        "LK:\n\t"
        "ld.shared.v2.b64 {p0, p1}, [pa];\n\t"
        "ld.shared.v2.b64 {xl0, xl1}, [xa];\n\t"
        "ld.shared.v2.b64 {xl2, xl3}, [xa+16];\n\t"
        "ld.shared.v2.b64 {xl4, xl5}, [xa+32];\n\t"
        "ld.shared.v2.b64 {xl6, xl7}, [xa+48];\n\t"
        // rows 0,1
        "add.rn.f32x2 t0, xl0, p0;  add.rn.f32x2 t1, xl0, p1;\n\t"
        "add.rn.f32x2 t2, xl1, p0;  add.rn.f32x2 t3, xl1, p1;\n\t"
        "and.b64 t0, t0, 0x7FFFFFFF7FFFFFFF; and.b64 t1, t1, 0x7FFFFFFF7FFFFFFF;\n\t"
        "and.b64 t2, t2, 0x7FFFFFFF7FFFFFFF; and.b64 t3, t3, 0x7FFFFFFF7FFFFFFF;\n\t"
        "add.rn.f32x2 a0, a0, t0;  add.rn.f32x2 a8, a8, t1;\n\t"
        "add.rn.f32x2 a1, a1, t2;  add.rn.f32x2 a9, a9, t3;\n\t"
        // rows 2,3
        "add.rn.f32x2 t0, xl2, p0;  add.rn.f32x2 t1, xl2, p1;\n\t"
        "add.rn.f32x2 t2, xl3, p0;  add.rn.f32x2 t3, xl3, p1;\n\t"
        "and.b64 t0, t0, 0x7FFFFFFF7FFFFFFF; and.b64 t1, t1, 0x7FFFFFFF7FFFFFFF;\n\t"
        "and.b64 t2, t2, 0x7FFFFFFF7FFFFFFF; and.b64 t3, t3, 0x7FFFFFFF7FFFFFFF;\n\t"
        "add.rn.f32x2 a2, a2, t0;  add.rn.f32x2 a10, a10, t1;\n\t"
        "add.rn.f32x2 a3, a3, t2;  add.rn.f32x2 a11, a11, t3;\n\t"
        // rows 4,5
        "add.rn.f32x2 t0, xl4, p0;  add.rn.f32x2 t1, xl4, p1;\n\t"
        "add.rn.f32x2 t2, xl5, p0;  add.rn.f32x2 t3, xl5, p1;\n\t"
        "and.b64 t0, t0, 0x7FFFFFFF7FFFFFFF; and.b64 t1, t1, 0x7FFFFFFF7FFFFFFF;\n\t"
        "and.b64 t2, t2, 0x7FFFFFFF7FFFFFFF; and.b64 t3, t3, 0x7FFFFFFF7FFFFFFF;\n\t"
        "add.rn.f32x2 a4, a4, t0;  add.rn.f32x2 a12, a12, t1;\n\t"
        "add.rn.f32x2 a5, a5, t2;  add.rn.f32x2 a13, a13, t3;\n\t"
        // rows 6,7
        "add.rn.f32x2 t0, xl6, p0;  add.rn.f32x2 t1, xl6, p1;\n\t"
        "add.rn.f32x2 t2, xl7, p0;  add.rn.f32x2 t3, xl7, p1;\n\t"
        "and.b64 t0, t0, 0x7FFFFFFF7FFFFFFF; and.b64 t1, t1, 0x7FFFFFFF7FFFFFFF;\n\t"
        "and.b64 t2, t2, 0x7FFFFFFF7FFFFFFF; and.b64 t3, t3, 0x7FFFFFFF7FFFFFFF;\n\t"
        "add.rn.f32x2 a6, a6, t0;  add.rn.f32x2 a14, a14, t1;\n\t"
        "add.rn.f32x2 a7, a7, t2;  add.rn.f32x2 a15, a15, t3;\n\t"
        // advance: 1 kk -> x += 512B, p += 256B
        "add.s32 xa, xa, 512;\n\t"
        "add.s32 pa, pa, 256;\n\t"
        "add.s32 k, k, 1;\n\t"
        "setp.lt.s32 lp, k, 32;\n\t"
        "@lp bra LK;\n\t"
        "mov.b64 %0, a0;   mov.b64 %1, a1;   mov.b64 %2, a2;   mov.b64 %3, a3;\n\t"
        "mov.b64 %4, a4;   mov.b64 %5, a5;   mov.b64 %6, a6;   mov.b64 %7, a7;\n\t"
        "mov.b64 %8, a8;   mov.b64 %9, a9;   mov.b64 %10, a10; mov.b64 %11, a11;\n\t"
        "mov.b64 %12, a12; mov.b64 %13, a13; mov.b64 %14, a14; mov.b64 %15, a15;\n\t"
        "}"
        : "=l"(A[0]), "=l"(A[1]), "=l"(A[2]), "=l"(A[3]),
          "=l"(A[4]), "=l"(A[5]), "=l"(A[6]), "=l"(A[7]),
          "=l"(A[8]), "=l"(A[9]), "=l"(A[10]), "=l"(A[11]),
          "=l"(A[12]), "=l"(A[13]), "=l"(A[14]), "=l"(A[15])
        : "r"(xa), "r"(pa)
        : "memory");

    // ---- horizontal pair sums ----
    float dist[8][2];
#pragma unroll
    for (int i = 0; i < 8; i++)
#pragma unroll
        for (int jj = 0; jj < 2; jj++) {
            ull a = A[i + 8 * jj];
            float lo = __uint_as_float((unsigned)(a & 0xFFFFFFFFull));
            float hi = __uint_as_float((unsigned)(a >> 32));
            dist[i][jj] = lo + hi;
        }

    // ---- write distances ----
#pragma unroll
    for (int i = 0; i < 8; i++) {
        size_t base = (size_t)(b0 + row0 + i) * V_TOTAL + v0;
        out[base + tx]      = dist[i][0];
        out[base + tx + 16] = dist[i][1];
    }

    // ---- row mins: butterfly over 16 tx lanes ----
#pragma unroll
    for (int i = 0; i < 8; i++) {
        float rm = fminf(dist[i][0], dist[i][1]);
        rm = fminf(rm, __shfl_xor_sync(0xFFFFFFFFu, rm, 1));
        rm = fminf(rm, __shfl_xor_sync(0xFFFFFFFFu, rm, 2));
        rm = fminf(rm, __shfl_xor_sync(0xFFFFFFFFu, rm, 4));
        rm = fminf(rm, __shfl_xor_sync(0xFFFFFFFFu, rm, 8));
        if (tx == 0)
            atomicMax(&g_rowmin_key[b0 + row0 + i], ~__float_as_uint(rm));
    }

    // ---- col mins ----
    float cm0 = dist[0][0], cm1 = dist[0][1];
#pragma unroll
    for (int i = 1; i < 8; i++) {
        cm0 = fminf(cm0, dist[i][0]);
        cm1 = fminf(cm1, dist[i][1]);
    }
    __syncthreads();
    unsigned int* cs = (unsigned int*)sm;   // [0..31] col keys, [64..71] red, [72] flag
    if (tid < TV) cs[tid] = 0u;
    __syncthreads();
    atomicMax(&cs[tx],      ~__float_as_uint(cm0));
    atomicMax(&cs[tx + 16], ~__float_as_uint(cm1));
    __syncthreads();
    if (tid < TV)
        atomicMax(&g_colmin_key[v0 + tid], cs[tid]);

    // ---- last-block finalize ----
    __threadfence();
    if (tid == 0)
        cs[72] = (atomicAdd(&g_arrive, 1u) == (unsigned)(NBLOCKS - 1)) ? 1u : 0u;
    __syncthreads();
    if (cs[72] == 0u) return;

    float s1 = 0.f, s2 = 0.f;
    for (int i = tid; i < V_TOTAL; i += 128)
        s1 += __uint_as_float(~__ldcg(&g_colmin_key[i]));
    for (int i = tid; i < B_TOTAL; i += 128)
        s2 += __uint_as_float(~__ldcg(&g_rowmin_key[i]));
#pragma unroll
    for (int o = 16; o > 0; o >>= 1) {
        s1 += __shfl_xor_sync(0xFFFFFFFFu, s1, o);
        s2 += __shfl_xor_sync(0xFFFFFFFFu, s2, o);
    }
    float* red = (float*)(cs + 64);
    int wid = tid >> 5;
    if ((tid & 31) == 0) { red[wid] = s1; red[4 + wid] = s2; }
    __syncthreads();
    if (tid == 0) {
        float r1 = red[0] + red[1] + red[2] + red[3];
        float r2 = red[4] + red[5] + red[6] + red[7];
        out[(size_t)B_TOTAL * V_TOTAL]     = r1 / (float)V_TOTAL;
        out[(size_t)B_TOTAL * V_TOTAL + 1] = r2 / (float)B_TOTAL;
        g_arrive = 0u;
    }
    for (int i = tid; i < B_TOTAL; i += 128) g_rowmin_key[i] = 0u;
    for (int i = tid; i < V_TOTAL; i += 128) g_colmin_key[i] = 0u;
}

extern "C" void kernel_launch(void* const* d_in, const int* in_sizes, int n_in,
                              void* d_out, int out_size) {
    (void)in_sizes; (void)n_in; (void)out_size;
    const float* x = (const float*)d_in[0];
    const float* p = (const float*)d_in[1];
    float* out = (float*)d_out;

    dim3 grid(V_TOTAL / TV, B_TOTAL / TB);   // (32, 64) = 2048 CTAs
    dist_fused<<<grid, 128>>>(x, p, out);
}

// round 8
// speedup vs baseline: 1.1375x; 1.1375x over previous
#include <cuda_runtime.h>

#define B_TOTAL 4096
#define V_TOTAL 1024
#define DD 64
#define TB 64
#define TV 32
#define NBLOCKS ((B_TOTAL / TB) * (V_TOTAL / TV))

// Zero-initialized scratch. Min stored as key = ~bits(value); dist >= 0 so bit
// order == value order, atomicMax(key) == min(value), 0 is the identity.
// Last block resets everything to 0 -> graph-replay safe.
__device__ unsigned int g_rowmin_key[B_TOTAL];
__device__ unsigned int g_colmin_key[V_TOTAL];
__device__ unsigned int g_arrive;

typedef unsigned long long ull;

__global__ __launch_bounds__(128, 6)
void dist_fused(const float* __restrict__ x, const float* __restrict__ p,
                float* __restrict__ out) {
    // 24 KB: sm[0..2047]      x pairs  XS(kk,row) = sm[kk*64 + row]
    //        sm[2048..3071]   p pairs  PS(kk,tx,j) = sm[2048 + kk*32 + tx*2 + j]
    // (each ull slot = one float2 = k-pair {2kk, 2kk+1})
    __shared__ ull sm[3072];

    const int tid = threadIdx.x;
    const int b0 = blockIdx.y * TB;
    const int v0 = blockIdx.x * TV;

    // ---- prologue (unchanged) ----
    if (tid < 64) {
        const float4* __restrict__ xr4 = (const float4*)(x + (size_t)(b0 + tid) * DD);
#pragma unroll
        for (int c4 = 0; c4 < 16; c4++) {
            float4 v = xr4[c4];
            int kk = c4 * 2;
            *(float2*)&sm[kk * 64 + tid]       = make_float2(v.x, v.y);
            *(float2*)&sm[(kk + 1) * 64 + tid] = make_float2(v.z, v.w);
        }
    } else {
        int t = tid - 64;
        int r = t & 31;
        int half = t >> 5;
        int lane16 = r & 15, jslot = r >> 4;
        const float4* __restrict__ pr4 = (const float4*)(p + (size_t)(v0 + r) * DD);
#pragma unroll
        for (int c4i = 0; c4i < 8; c4i++) {
            int c4 = half * 8 + c4i;
            float4 v = pr4[c4];
            int kk = c4 * 2;
            *(float2*)&sm[2048 + kk * 32 + lane16 * 2 + jslot]       = make_float2(-v.x, -v.y);
            *(float2*)&sm[2048 + (kk + 1) * 32 + lane16 * 2 + jslot] = make_float2(-v.z, -v.w);
        }
    }
    __syncthreads();

    const int tx = tid & 15;    // v = tx (j=0), tx+16 (j=1)
    const int ty = tid >> 4;    // rows ty*8 .. ty*8+7
    const int row0 = ty * 8;

    const float2* __restrict__ xf = (const float2*)sm + row0;          // [kk*64 + i]
    const float2* __restrict__ pf = (const float2*)sm + 2048 + tx * 2; // [kk*32 + j]

    // scalar accumulators: ax[i][j] for k-even, ay[i][j] for k-odd
    float ax[8][2], ay[8][2];
#pragma unroll
    for (int i = 0; i < 8; i++)
#pragma unroll
        for (int j = 0; j < 2; j++) { ax[i][j] = 0.f; ay[i][j] = 0.f; }

#pragma unroll 4
    for (int kk = 0; kk < 32; kk++) {
        // p pair for both columns: adjacent float2 -> one LDS.128
        float2 P0 = pf[kk * 32 + 0];
        float2 P1 = pf[kk * 32 + 1];
#pragma unroll
        for (int i = 0; i < 8; i++) {
            float2 X = xf[kk * 64 + i];   // adjacent i -> LDS.128 pairs
            // d = x - p  (p pre-negated); acc += |d|  (abs folds into FADD/FFMA src)
            float d00 = X.x + P0.x;
            float d01 = X.x + P1.x;
            float d10 = X.y + P0.y;
            float d11 = X.y + P1.y;
            ax[i][0] = __fmaf_rn(fabsf(d00), 1.0f, ax[i][0]);
            ax[i][1] = __fmaf_rn(fabsf(d01), 1.0f, ax[i][1]);
            ay[i][0] = __fmaf_rn(fabsf(d10), 1.0f, ay[i][0]);
            ay[i][1] = __fmaf_rn(fabsf(d11), 1.0f, ay[i][1]);
        }
    }

    // ---- combine even/odd partials ----
    float dist[8][2];
#pragma unroll
    for (int i = 0; i < 8; i++)
#pragma unroll
        for (int j = 0; j < 2; j++)
            dist[i][j] = ax[i][j] + ay[i][j];

    // ---- write distances ----
#pragma unroll
    for (int i = 0; i < 8; i++) {
        size_t base = (size_t)(b0 + row0 + i) * V_TOTAL + v0;
        out[base + tx]      = dist[i][0];
        out[base + tx + 16] = dist[i][1];
    }

    // ---- row mins: butterfly over 16 tx lanes ----
#pragma unroll
    for (int i = 0; i < 8; i++) {
        float rm = fminf(dist[i][0], dist[i][1]);
        rm = fminf(rm, __shfl_xor_sync(0xFFFFFFFFu, rm, 1));
        rm = fminf(rm, __shfl_xor_sync(0xFFFFFFFFu, rm, 2));
        rm = fminf(rm, __shfl_xor_sync(0xFFFFFFFFu, rm, 4));
        rm = fminf(rm, __shfl_xor_sync(0xFFFFFFFFu, rm, 8));
        if (tx == 0)
            atomicMax(&g_rowmin_key[b0 + row0 + i], ~__float_as_uint(rm));
    }

    // ---- col mins ----
    float cm0 = dist[0][0], cm1 = dist[0][1];
#pragma unroll
    for (int i = 1; i < 8; i++) {
        cm0 = fminf(cm0, dist[i][0]);
        cm1 = fminf(cm1, dist[i][1]);
    }
    __syncthreads();
    unsigned int* cs = (unsigned int*)sm;   // [0..31] col keys, [64..71] red, [72] flag
    if (tid < TV) cs[tid] = 0u;
    __syncthreads();
    atomicMax(&cs[tx],      ~__float_as_uint(cm0));
    atomicMax(&cs[tx + 16], ~__float_as_uint(cm1));
    __syncthreads();
    if (tid < TV)
        atomicMax(&g_colmin_key[v0 + tid], cs[tid]);

    // ---- last-block finalize ----
    __threadfence();
    if (tid == 0)
        cs[72] = (atomicAdd(&g_arrive, 1u) == (unsigned)(NBLOCKS - 1)) ? 1u : 0u;
    __syncthreads();
    if (cs[72] == 0u) return;

    float s1 = 0.f, s2 = 0.f;
    for (int i = tid; i < V_TOTAL; i += 128)
        s1 += __uint_as_float(~__ldcg(&g_colmin_key[i]));
    for (int i = tid; i < B_TOTAL; i += 128)
        s2 += __uint_as_float(~__ldcg(&g_rowmin_key[i]));
#pragma unroll
    for (int o = 16; o > 0; o >>= 1) {
        s1 += __shfl_xor_sync(0xFFFFFFFFu, s1, o);
        s2 += __shfl_xor_sync(0xFFFFFFFFu, s2, o);
    }
    float* red = (float*)(cs + 64);
    int wid = tid >> 5;
    if ((tid & 31) == 0) { red[wid] = s1; red[4 + wid] = s2; }
    __syncthreads();
    if (tid == 0) {
        float r1 = red[0] + red[1] + red[2] + red[3];
        float r2 = red[4] + red[5] + red[6] + red[7];
        out[(size_t)B_TOTAL * V_TOTAL]     = r1 / (float)V_TOTAL;
        out[(size_t)B_TOTAL * V_TOTAL + 1] = r2 / (float)B_TOTAL;
        g_arrive = 0u;
    }
    for (int i = tid; i < B_TOTAL; i += 128) g_rowmin_key[i] = 0u;
    for (int i = tid; i < V_TOTAL; i += 128) g_colmin_key[i] = 0u;
}

extern "C" void kernel_launch(void* const* d_in, const int* in_sizes, int n_in,
                              void* d_out, int out_size) {
    (void)in_sizes; (void)n_in; (void)out_size;
    const float* x = (const float*)d_in[0];
    const float* p = (const float*)d_in[1];
    float* out = (float*)d_out;

    dim3 grid(V_TOTAL / TV, B_TOTAL / TB);   // (32, 64) = 2048 CTAs
    dist_fused<<<grid, 128>>>(x, p, out);
}

// round 10
// speedup vs baseline: 1.1415x; 1.0035x over previous
#include <cuda_runtime.h>

#define B_TOTAL 4096
#define V_TOTAL 1024
#define DD 64
#define TB 64
#define TV 32
#define NBLOCKS ((B_TOTAL / TB) * (V_TOTAL / TV))

// Zero-initialized scratch. Min stored as key = ~bits(value); dist >= 0 so bit
// order == value order, atomicMax(key) == min(value), 0 is the identity.
// Last block resets everything to 0 -> graph-replay safe.
__device__ unsigned int g_rowmin_key[B_TOTAL];
__device__ unsigned int g_colmin_key[V_TOTAL];
__device__ unsigned int g_arrive;

typedef unsigned long long ull;

__global__ __launch_bounds__(128, 6)
void dist_fused(const float* __restrict__ x, const float* __restrict__ p,
                float* __restrict__ out) {
    // 24 KB: sm[0..2047]      x pairs (PRE-SCALED by 0.5)  XS(kk,row) = sm[kk*64 + row]
    //        sm[2048..3071]   p pairs (raw)                PS(kk,tx,j) = sm[2048 + kk*32 + tx*2 + j]
    __shared__ ull sm[3072];

    const int tid = threadIdx.x;
    const int b0 = blockIdx.y * TB;
    const int v0 = blockIdx.x * TV;

    // ---- prologue: x scaled by 0.5 (exact), p raw ----
    if (tid < 64) {
        const float4* __restrict__ xr4 = (const float4*)(x + (size_t)(b0 + tid) * DD);
#pragma unroll
        for (int c4 = 0; c4 < 16; c4++) {
            float4 v = xr4[c4];
            int kk = c4 * 2;
            *(float2*)&sm[kk * 64 + tid]       = make_float2(0.5f * v.x, 0.5f * v.y);
            *(float2*)&sm[(kk + 1) * 64 + tid] = make_float2(0.5f * v.z, 0.5f * v.w);
        }
    } else {
        int t = tid - 64;
        int r = t & 31;
        int half = t >> 5;
        int lane16 = r & 15, jslot = r >> 4;
        const float4* __restrict__ pr4 = (const float4*)(p + (size_t)(v0 + r) * DD);
#pragma unroll
        for (int c4i = 0; c4i < 8; c4i++) {
            int c4 = half * 8 + c4i;
            float4 v = pr4[c4];
            int kk = c4 * 2;
            *(float2*)&sm[2048 + kk * 32 + lane16 * 2 + jslot]       = make_float2(v.x, v.y);
            *(float2*)&sm[2048 + (kk + 1) * 32 + lane16 * 2 + jslot] = make_float2(v.z, v.w);
        }
    }
    __syncthreads();

    const int tx = tid & 15;    // v = tx (j=0), tx+16 (j=1)
    const int ty = tid >> 4;    // rows ty*8 .. ty*8+7
    const int row0 = ty * 8;

    const float2* __restrict__ xf = (const float2*)sm + row0;          // [kk*64 + i]
    const float2* __restrict__ pf = (const float2*)sm + 2048 + tx * 2; // [kk*32 + j]

    // accumulators hold 0.5 * sum|x-p| (exact scaling; x2 at the end)
    float ax[8][2], ay[8][2];
#pragma unroll
    for (int i = 0; i < 8; i++)
#pragma unroll
        for (int j = 0; j < 2; j++) { ax[i][j] = 0.f; ay[i][j] = 0.f; }

#pragma unroll 4
    for (int kk = 0; kk < 32; kk++) {
        float2 P0 = pf[kk * 32 + 0];   // adjacent -> one LDS.128
        float2 P1 = pf[kk * 32 + 1];
#pragma unroll
        for (int i = 0; i < 8; i++) {
            float2 X = xf[kk * 64 + i];   // adjacent i -> LDS.128 pairs
            // d = 0.5x - 0.5p via FFMA-imm (rt 1: -0.5 cannot canonicalize to FADD)
            float d00 = __fmaf_rn(P0.x, -0.5f, X.x);
            float d01 = __fmaf_rn(P1.x, -0.5f, X.x);
            float d10 = __fmaf_rn(P0.y, -0.5f, X.y);
            float d11 = __fmaf_rn(P1.y, -0.5f, X.y);
            // acc += |d| -> FADD with |src| modifier (proven fold, rt 2)
            ax[i][0] += fabsf(d00);
            ax[i][1] += fabsf(d01);
            ay[i][0] += fabsf(d10);
            ay[i][1] += fabsf(d11);
        }
    }

    // ---- combine even/odd partials, undo exact 0.5 scaling ----
    float dist[8][2];
#pragma unroll
    for (int i = 0; i < 8; i++)
#pragma unroll
        for (int j = 0; j < 2; j++)
            dist[i][j] = 2.0f * (ax[i][j] + ay[i][j]);

    // ---- write distances ----
#pragma unroll
    for (int i = 0; i < 8; i++) {
        size_t base = (size_t)(b0 + row0 + i) * V_TOTAL + v0;
        out[base + tx]      = dist[i][0];
        out[base + tx + 16] = dist[i][1];
    }

    // ---- row mins: butterfly over 16 tx lanes ----
#pragma unroll
    for (int i = 0; i < 8; i++) {
        float rm = fminf(dist[i][0], dist[i][1]);
        rm = fminf(rm, __shfl_xor_sync(0xFFFFFFFFu, rm, 1));
        rm = fminf(rm, __shfl_xor_sync(0xFFFFFFFFu, rm, 2));
        rm = fminf(rm, __shfl_xor_sync(0xFFFFFFFFu, rm, 4));
        rm = fminf(rm, __shfl_xor_sync(0xFFFFFFFFu, rm, 8));
        if (tx == 0)
            atomicMax(&g_rowmin_key[b0 + row0 + i], ~__float_as_uint(rm));
    }

    // ---- col mins ----
    float cm0 = dist[0][0], cm1 = dist[0][1];
#pragma unroll
    for (int i = 1; i < 8; i++) {
        cm0 = fminf(cm0, dist[i][0]);
        cm1 = fminf(cm1, dist[i][1]);
    }
    __syncthreads();
    unsigned int* cs = (unsigned int*)sm;   // [0..31] col keys, [64..71] red, [72] flag
    if (tid < TV) cs[tid] = 0u;
    __syncthreads();
    atomicMax(&cs[tx],      ~__float_as_uint(cm0));
    atomicMax(&cs[tx + 16], ~__float_as_uint(cm1));
    __syncthreads();
    if (tid < TV)
        atomicMax(&g_colmin_key[v0 + tid], cs[tid]);

    // ---- last-block finalize ----
    __threadfence();
    if (tid == 0)
        cs[72] = (atomicAdd(&g_arrive, 1u) == (unsigned)(NBLOCKS - 1)) ? 1u : 0u;
    __syncthreads();
    if (cs[72] == 0u) return;

    float s1 = 0.f, s2 = 0.f;
    for (int i = tid; i < V_TOTAL; i += 128)
        s1 += __uint_as_float(~__ldcg(&g_colmin_key[i]));
    for (int i = tid; i < B_TOTAL; i += 128)
        s2 += __uint_as_float(~__ldcg(&g_rowmin_key[i]));
#pragma unroll
    for (int o = 16; o > 0; o >>= 1) {
        s1 += __shfl_xor_sync(0xFFFFFFFFu, s1, o);
        s2 += __shfl_xor_sync(0xFFFFFFFFu, s2, o);
    }
    float* red = (float*)(cs + 64);
    int wid = tid >> 5;
    if ((tid & 31) == 0) { red[wid] = s1; red[4 + wid] = s2; }
    __syncthreads();
    if (tid == 0) {
        float r1 = red[0] + red[1] + red[2] + red[3];
        float r2 = red[4] + red[5] + red[6] + red[7];
        out[(size_t)B_TOTAL * V_TOTAL]     = r1 / (float)V_TOTAL;
        out[(size_t)B_TOTAL * V_TOTAL + 1] = r2 / (float)B_TOTAL;
        g_arrive = 0u;
    }
    for (int i = tid; i < B_TOTAL; i += 128) g_rowmin_key[i] = 0u;
    for (int i = tid; i < V_TOTAL; i += 128) g_colmin_key[i] = 0u;
}

extern "C" void kernel_launch(void* const* d_in, const int* in_sizes, int n_in,
                              void* d_out, int out_size) {
    (void)in_sizes; (void)n_in; (void)out_size;
    const float* x = (const float*)d_in[0];
    const float* p = (const float*)d_in[1];
    float* out = (float*)d_out;

    dim3 grid(V_TOTAL / TV, B_TOTAL / TB);   // (32, 64) = 2048 CTAs
    dist_fused<<<grid, 128>>>(x, p, out);
}